// round 15
// baseline (speedup 1.0000x reference)
#include <cuda_runtime.h>
#include <cuda_bf16.h>
#include <cuda_fp16.h>
#include <math.h>
#include <stdint.h>

#define TT 2048
#define DD 1024
#define EE 8
#define FF 2048
#define NSLOT (TT*2)
#define NW (EE*FF*DD)

#define S_ACT 16.f
#define S_WGT 512.f
#define INV_ACC (1.f/8192.f)

// ---------------- scratch ----------------
__device__ __align__(16) uint8_t g_xn8[TT*DD];
__device__ __align__(16) uint8_t g_w1_8[NW];
__device__ __align__(16) uint8_t g_w2_8[NW];
__device__ __align__(16) uint8_t g_h8[(size_t)NSLOT*FF];
__device__ __align__(16) __half g_yh[(size_t)NSLOT*DD];
__device__ float g_probs[TT*EE];
__device__ int   g_slot_e[NSLOT];
__device__ float g_slot_w[NSLOT];
__device__ int   g_slot_row[NSLOT];
__device__ int   g_row_tok[NSLOT];
__device__ int   g_n[EE];
__device__ int   g_off[EE];
__device__ int   g_cnt1[EE];

// ================= helpers =================
__device__ __forceinline__ uint32_t smem_u32(const void* p) {
    uint32_t a;
    asm("{ .reg .u64 t; cvta.to.shared.u64 t, %1; cvt.u32.u64 %0, t; }" : "=r"(a) : "l"(p));
    return a;
}
__device__ __forceinline__ void cpa16(uint32_t dst, const void* src) {
    asm volatile("cp.async.cg.shared.global [%0], [%1], 16;" :: "r"(dst), "l"(src) : "memory");
}
#define CP_COMMIT() asm volatile("cp.async.commit_group;" ::: "memory")
#define CP_WAIT1()  asm volatile("cp.async.wait_group 1;" ::: "memory")

__device__ __forceinline__ void ldsm_x4(uint32_t (&r)[4], uint32_t addr) {
    asm volatile("ldmatrix.sync.aligned.m8n8.x4.shared.b16 {%0,%1,%2,%3}, [%4];"
        : "=r"(r[0]), "=r"(r[1]), "=r"(r[2]), "=r"(r[3]) : "r"(addr));
}
__device__ __forceinline__ void mma_fp8h(uint32_t (&d)[2], const uint32_t (&a)[4],
                                         uint32_t b0, uint32_t b1) {
    asm volatile("mma.sync.aligned.m16n8k32.row.col.f16.e4m3.e4m3.f16 "
        "{%0,%1}, {%2,%3,%4,%5}, {%6,%7}, {%0,%1};"
        : "+r"(d[0]), "+r"(d[1])
        : "r"(a[0]), "r"(a[1]), "r"(a[2]), "r"(a[3]), "r"(b0), "r"(b1));
}
__device__ __forceinline__ uint16_t cvt_e4m3x2(float lo, float hi) {
    uint16_t h;
    asm("cvt.rn.satfinite.e4m3x2.f32 %0, %1, %2;" : "=h"(h) : "f"(hi), "f"(lo));
    return h;
}
__device__ __forceinline__ uint32_t rowu_rel(int row, int u) {
    return (uint32_t)row*80u + (uint32_t)((u ^ ((row >> 3) & 3)) * 16);
}
__device__ __forceinline__ float wred(float v) {
#pragma unroll
    for (int d = 16; d > 0; d >>= 1) v += __shfl_down_sync(0xffffffffu, v, d);
    return v;
}

// ---------------- fp32 -> fp8 conversion (one tensor) ------------------------
__global__ void k_cvt8(const float4* __restrict__ in, uint2* __restrict__ outp)
{
    int i = blockIdx.x*256 + threadIdx.x;
    float4 a = in[2*i], b = in[2*i+1];
    uint32_t u0 = (uint32_t)cvt_e4m3x2(a.x*S_WGT, a.y*S_WGT)
                | ((uint32_t)cvt_e4m3x2(a.z*S_WGT, a.w*S_WGT) << 16);
    uint32_t u1 = (uint32_t)cvt_e4m3x2(b.x*S_WGT, b.y*S_WGT)
                | ((uint32_t)cvt_e4m3x2(b.z*S_WGT, b.w*S_WGT) << 16);
    outp[i] = make_uint2(u0, u1);
}

// ---------------- kernel 1: rmsnorm + router ---------------------------------
__global__ void k_norm_router(const float* __restrict__ x,
                              const float* __restrict__ gw,
                              const float* __restrict__ nw)
{
    int t = blockIdx.x, tid = threadIdx.x, lane = tid & 31, w = tid >> 5;
    __shared__ float wss[8];
    __shared__ float wr8[8][8];
    __shared__ float pfin[8];

    const float4* x4 = reinterpret_cast<const float4*>(x) + (size_t)t*256;
    float4 xv = x4[tid];
    float ss = xv.x*xv.x + xv.y*xv.y + xv.z*xv.z + xv.w*xv.w;
    ss = wred(ss);
    if (lane == 0) wss[w] = ss;
    __syncthreads();
    float tot = wss[0]+wss[1]+wss[2]+wss[3]+wss[4]+wss[5]+wss[6]+wss[7];
    float rstd = rsqrtf(tot*(1.0f/1024.0f) + 1.1920928955078125e-07f);

    float4 wv = reinterpret_cast<const float4*>(nw)[tid];
    float4 xn;
    xn.x = xv.x*rstd*wv.x; xn.y = xv.y*rstd*wv.y;
    xn.z = xv.z*rstd*wv.z; xn.w = xv.w*rstd*wv.w;
    uint32_t pk = (uint32_t)cvt_e4m3x2(xn.x*S_ACT, xn.y*S_ACT)
                | ((uint32_t)cvt_e4m3x2(xn.z*S_ACT, xn.w*S_ACT) << 16);
    reinterpret_cast<uint32_t*>(g_xn8)[(size_t)t*256 + tid] = pk;

    const float4* gw4 = reinterpret_cast<const float4*>(gw);
#pragma unroll
    for (int e = 0; e < 8; e++) {
        float4 g = gw4[e*256 + tid];
        float r = xn.x*g.x + xn.y*g.y + xn.z*g.z + xn.w*g.w;
        r = wred(r);
        if (lane == 0) wr8[w][e] = r;
    }
    __syncthreads();
    if (w == 0 && lane < 8) {
        float s = 0.f;
#pragma unroll
        for (int k = 0; k < 8; k++) s += wr8[k][lane];
        pfin[lane] = s;
    }
    __syncthreads();

    if (tid == 0) {
        float p[8]; float m = -1e30f;
#pragma unroll
        for (int e = 0; e < 8; e++) { p[e] = pfin[e]; m = fmaxf(m, p[e]); }
        float s = 0.f;
#pragma unroll
        for (int e = 0; e < 8; e++) { p[e] = expf(p[e]-m); s += p[e]; }
        float inv = 1.f/s;
#pragma unroll
        for (int e = 0; e < 8; e++) { p[e] *= inv; g_probs[t*8+e] = p[e]; }
        int e0 = 0;
#pragma unroll
        for (int e = 1; e < 8; e++) if (p[e] > p[e0]) e0 = e;
        int e1 = (e0 == 0) ? 1 : 0;
#pragma unroll
        for (int e = 0; e < 8; e++) if (e != e0 && p[e] > p[e1]) e1 = e;
        float swt = fmaxf(p[e0] + p[e1], 1e-6f);
        g_slot_e[2*t]   = e0; g_slot_e[2*t+1] = e1;
        g_slot_w[2*t]   = p[e0]/swt;
        g_slot_w[2*t+1] = p[e1]/swt;
    }
}

// -------- kernel 2: count + offsets + stable placement -----------------------
__global__ void k_place()
{
    int e = blockIdx.x, tid = threadIdx.x, lane = tid & 31, w = tid >> 5;
    __shared__ int tot[8];
    __shared__ int c1tot;
    __shared__ int wsum[8];

    int se[16];
    int c8[8] = {0,0,0,0,0,0,0,0};
    int c1 = 0;
    int base_i = tid * 16;
#pragma unroll
    for (int j = 0; j < 16; j++) {
        int s = g_slot_e[base_i + j];
        se[j] = s;
        c8[s]++;
        if ((((base_i + j) & 1) == 0) && s == e) c1++;
    }
    int cnt = c8[e];
    if (tid < 8) tot[tid] = 0;
    if (tid == 0) c1tot = 0;
    __syncthreads();
#pragma unroll
    for (int k = 0; k < 8; k++) if (c8[k]) atomicAdd(&tot[k], c8[k]);
    if (c1) atomicAdd(&c1tot, c1);

    int pre = cnt;
#pragma unroll
    for (int d = 1; d < 32; d <<= 1) {
        int v = __shfl_up_sync(0xffffffffu, pre, d);
        if (lane >= d) pre += v;
    }
    if (lane == 31) wsum[w] = pre;
    __syncthreads();

    int woff = 0;
#pragma unroll
    for (int k = 0; k < 8; k++) if (k < w) woff += wsum[k];
    int excl = woff + pre - cnt;

    int base = 0;
#pragma unroll
    for (int k = 0; k < 8; k++) if (k < e) base += tot[k];
    if (tid == 0) { g_n[e] = tot[e]; g_off[e] = base; g_cnt1[e] = c1tot; }

    int pos = base + excl;
#pragma unroll
    for (int j = 0; j < 16; j++) {
        if (se[j] == e) {
            g_slot_row[base_i + j] = pos;
            g_row_tok[pos] = (base_i + j) >> 1;
            pos++;
        }
    }
}

// ---------------- grouped fp8 GEMM, f16 acc, 3-stage ring --------------------
// TILE_N: CTA N tile (128 or 64). Warp layout 2 row x 4 col, warp tile 64 x TILE_N/4.
// OUTMODE: 0 = silu + fp8 out (gemm1), 1 = f16 out (gemm2).
template<int TILE_N, int MINB, int OUTMODE, bool GATHER>
__global__ void __launch_bounds__(256, MINB) gemm_fp8(
    const uint8_t* __restrict__ A,
    const uint8_t* __restrict__ Bw,
    void* __restrict__ Cv,
    int ldaB, int kdB, int ldc, size_t bstrideB, int ebase)
{
    constexpr int WT_N = TILE_N / 4;          // 32 or 16
    constexpr int NI   = WT_N / 8;            // 4 or 2
    constexpr int NB   = (NI + 1) / 2;        // 2 or 1
    constexpr int BSEG = TILE_N / 64;         // 2 or 1 (16B units per thread)
    constexpr uint32_t STG = (uint32_t)(128 + TILE_N) * 80u;
    constexpr uint32_t RING = 3u * STG;
    constexpr uint32_t bOff = 128 * 80;

    int e = ebase + blockIdx.z;
    int n_e = g_n[e];
    int rowBase = blockIdx.y * 128;
    if (rowBase >= n_e) return;
    int off = g_off[e];
    int colBase = blockIdx.x * TILE_N;

    extern __shared__ char smraw[];
    uint32_t sm0 = smem_u32(smraw);

    int tid = threadIdx.x, wid = tid >> 5, lane = tid & 31;
    int rowWarp = wid & 1, colWarp = wid >> 1;

    // A loads: 128 rows x 4 units, 2 units/thread
    int aR = tid >> 1;
    int aS = (tid & 1) * 2;
    const uint8_t* aRow;
    {
        int src;
        if (GATHER) src = (rowBase + aR < n_e) ? g_row_tok[off + rowBase + aR] : 0;
        else { int gr = off + rowBase + aR; src = (gr < NSLOT) ? gr : 0; }
        aRow = A + (size_t)src * ldaB + aS*16;
    }
    uint32_t aDst0 = sm0 + rowu_rel(aR, aS);
    uint32_t aDst1 = sm0 + rowu_rel(aR, aS + 1);

    // B loads: TILE_N rows x 4 units, BSEG units/thread
    int bR = (BSEG == 2) ? (tid >> 1) : (tid >> 2);
    int bS = (BSEG == 2) ? ((tid & 1) * 2) : (tid & 3);
    const uint8_t* bRow = Bw + (size_t)e * bstrideB + (size_t)(colBase + bR) * kdB + bS*16;
    uint32_t bDst[BSEG];
#pragma unroll
    for (int j = 0; j < BSEG; j++) bDst[j] = sm0 + bOff + rowu_rel(bR, bS + j);

    // ldmatrix lane addresses
    int lr = lane & 15, hiU = lane >> 4;
    int nl = (lane & 7) + ((lane & 16) ? 8 : 0);
    int kcU = (lane >> 3) & 1;
    uint32_t aAddr[2][4], bAddr[2][NB];
#pragma unroll
    for (int ks = 0; ks < 2; ks++) {
#pragma unroll
        for (int mi = 0; mi < 4; mi++)
            aAddr[ks][mi] = sm0 + rowu_rel(rowWarp*64 + mi*16 + lr, ks*2 + hiU);
#pragma unroll
        for (int nb = 0; nb < NB; nb++)
            bAddr[ks][nb] = sm0 + bOff + rowu_rel(colWarp*WT_N + nb*16 + nl, ks*2 + kcU);
    }

    uint32_t acc[4][NI][2];
#pragma unroll
    for (int mi = 0; mi < 4; mi++)
#pragma unroll
        for (int ni = 0; ni < NI; ni++) { acc[mi][ni][0] = 0u; acc[mi][ni][1] = 0u; }

    int nch = kdB >> 6;

#define ISSUE(KB, SO) do { \
    const uint8_t* _as = aRow + (KB)*64; \
    cpa16(aDst0 + (SO), _as); cpa16(aDst1 + (SO), _as + 16); \
    const uint8_t* _bs = bRow + (KB)*64; \
    _Pragma("unroll") \
    for (int _j = 0; _j < BSEG; _j++) cpa16(bDst[_j] + (SO), _bs + _j*16); \
    CP_COMMIT(); } while (0)

    ISSUE(0, 0u); ISSUE(1, STG);

    uint32_t soC = 0, soI = 2u * STG;
    for (int kb = 0; kb < nch; kb++) {
        CP_WAIT1();
        __syncthreads();
        if (kb + 2 < nch) { ISSUE(kb + 2, soI); } else { CP_COMMIT(); }
        soI += STG; if (soI == RING) soI = 0;

#pragma unroll
        for (int ks = 0; ks < 2; ks++) {
            uint32_t af[4][4], bf[NB][4];
#pragma unroll
            for (int mi = 0; mi < 4; mi++)
                ldsm_x4(af[mi], aAddr[ks][mi] + soC);
#pragma unroll
            for (int nb = 0; nb < NB; nb++)
                ldsm_x4(bf[nb], bAddr[ks][nb] + soC);
#pragma unroll
            for (int mi = 0; mi < 4; mi++) {
#pragma unroll
                for (int ni = 0; ni < NI; ni++)
                    mma_fp8h(acc[mi][ni], af[mi], bf[ni>>1][(ni&1)*2], bf[ni>>1][(ni&1)*2+1]);
            }
        }
        soC += STG; if (soC == RING) soC = 0;
    }
#undef ISSUE

    int g  = lane >> 2;
    int tq = lane & 3;
    const __half2 hInv = __float2half2_rn(INV_ACC);
#pragma unroll
    for (int mi = 0; mi < 4; mi++) {
#pragma unroll
        for (int half_ = 0; half_ < 2; half_++) {
            int rr = rowBase + rowWarp*64 + mi*16 + half_*8 + g;
            if (rr >= n_e) continue;
            size_t rowOff = (size_t)(off + rr) * ldc;
#pragma unroll
            for (int ni = 0; ni < NI; ni++) {
                int c = colBase + colWarp*WT_N + ni*8 + tq*2;
                __half2 hv = *reinterpret_cast<__half2*>(&acc[mi][ni][half_]);
                if (OUTMODE == 0) {
                    float2 f = __half22float2(hv);
                    float v0 = f.x * INV_ACC;
                    float v1 = f.y * INV_ACC;
                    v0 = v0 / (1.f + expf(-v0));
                    v1 = v1 / (1.f + expf(-v1));
                    uint16_t hq = cvt_e4m3x2(v0*S_ACT, v1*S_ACT);
                    *reinterpret_cast<uint16_t*>(
                        reinterpret_cast<uint8_t*>(Cv) + rowOff + c) = hq;
                } else {
                    __half2 y = __hmul2(hv, hInv);
                    *reinterpret_cast<__half2*>(
                        reinterpret_cast<__half*>(Cv) + rowOff + c) = y;
                }
            }
        }
    }
}

// ---------------- residual + weighted combine (+ lb loss) --------------------
__global__ void k_combine(const float* __restrict__ x,
                          const float* __restrict__ scale,
                          float* __restrict__ out, int out_size)
{
    int t = blockIdx.x, q = threadIdx.x;
    float sc = 1.f / (1.f + expf(-scale[0]));
    int   r0 = g_slot_row[2*t],   r1 = g_slot_row[2*t+1];
    float w0 = g_slot_w[2*t],     w1 = g_slot_w[2*t+1];
    const float4* x4 = reinterpret_cast<const float4*>(x);
    const __half2* y2 = reinterpret_cast<const __half2*>(g_yh);
    float4 xv = x4[(size_t)t*256 + q];
    __half2 a0 = y2[(size_t)r0*512 + q*2],  a1 = y2[(size_t)r0*512 + q*2 + 1];
    __half2 b0 = y2[(size_t)r1*512 + q*2],  b1 = y2[(size_t)r1*512 + q*2 + 1];
    float2 fa0 = __half22float2(a0), fa1 = __half22float2(a1);
    float2 fb0 = __half22float2(b0), fb1 = __half22float2(b1);
    float4 o;
    o.x = xv.x + sc*(w0*fa0.x + w1*fb0.x);
    o.y = xv.y + sc*(w0*fa0.y + w1*fb0.y);
    o.z = xv.z + sc*(w0*fa1.x + w1*fb1.x);
    o.w = xv.w + sc*(w0*fa1.y + w1*fb1.y);
    reinterpret_cast<float4*>(out)[(size_t)t*256 + q] = o;

    if (t == 0 && out_size > TT*DD) {
        __shared__ float r8[8*256];
        float p[8] = {0.f,0.f,0.f,0.f,0.f,0.f,0.f,0.f};
        for (int tt = q; tt < TT; tt += 256) {
#pragma unroll
            for (int e = 0; e < 8; e++) p[e] += g_probs[tt*8+e];
        }
#pragma unroll
        for (int e = 0; e < 8; e++) r8[e*256+q] = p[e];
        __syncthreads();
        for (int s = 128; s > 0; s >>= 1) {
            if (q < s) {
#pragma unroll
                for (int e = 0; e < 8; e++) r8[e*256+q] += r8[e*256+q+s];
            }
            __syncthreads();
        }
        if (q == 0) {
            float lb = 0.f;
            for (int e = 0; e < 8; e++) {
                float fe = (float)g_cnt1[e] * (1.f/(float)TT);
                float pm = r8[e*256] * (1.f/(float)TT);
                lb += fe * pm;
            }
            out[(size_t)TT*DD] = 8.f * lb;
        }
    }
}

// ------ launch: round-10 schedule, both GEMMs retiled to N=64 ----------------
extern "C" void kernel_launch(void* const* d_in, const int* in_sizes, int n_in,
                              void* d_out, int out_size)
{
    const float* x     = (const float*)d_in[0];
    const float* gw    = (const float*)d_in[1];
    const float* w1    = (const float*)d_in[2];
    const float* w2    = (const float*)d_in[3];
    const float* nw    = (const float*)d_in[4];
    const float* scale = (const float*)d_in[5];
    float* out = (float*)d_out;

    uint8_t *p_xn8, *p_w1_8, *p_w2_8, *p_h8;
    __half *p_yh;
    cudaGetSymbolAddress((void**)&p_xn8,  g_xn8);
    cudaGetSymbolAddress((void**)&p_w1_8, g_w1_8);
    cudaGetSymbolAddress((void**)&p_w2_8, g_w2_8);
    cudaGetSymbolAddress((void**)&p_h8,   g_h8);
    cudaGetSymbolAddress((void**)&p_yh,   g_yh);

    const int DSM64 = (128 + 64) * 80 * 3;   // 46080
    static cudaStream_t s1, s2;
    static cudaEvent_t evFork, evW1, evW2, evPlace, evB;
    static bool init_done = false;
    if (!init_done) {
        cudaFuncSetAttribute((const void*)gemm_fp8<64, 3, 0, true >,
                             cudaFuncAttributeMaxDynamicSharedMemorySize, DSM64);
        cudaFuncSetAttribute((const void*)gemm_fp8<64, 3, 1, false>,
                             cudaFuncAttributeMaxDynamicSharedMemorySize, DSM64);
        cudaStreamCreateWithFlags(&s1, cudaStreamNonBlocking);
        cudaStreamCreateWithFlags(&s2, cudaStreamNonBlocking);
        cudaEventCreateWithFlags(&evFork,  cudaEventDisableTiming);
        cudaEventCreateWithFlags(&evW1,    cudaEventDisableTiming);
        cudaEventCreateWithFlags(&evW2,    cudaEventDisableTiming);
        cudaEventCreateWithFlags(&evPlace, cudaEventDisableTiming);
        cudaEventCreateWithFlags(&evB,     cudaEventDisableTiming);
        init_done = true;
    }

    // fork: weight conversion on side stream s1
    cudaEventRecord(evFork, 0);
    cudaStreamWaitEvent(s1, evFork, 0);
    k_cvt8<<<NW/8/256, 256, 0, s1>>>((const float4*)w1, (uint2*)p_w1_8);
    cudaEventRecord(evW1, s1);
    k_cvt8<<<NW/8/256, 256, 0, s1>>>((const float4*)w2, (uint2*)p_w2_8);
    cudaEventRecord(evW2, s1);

    // main: norm + router + placement
    k_norm_router<<<TT, 256>>>(x, gw, nw);
    k_place<<<EE, 256>>>();
    cudaEventRecord(evPlace, 0);

    dim3 grid1(FF/64, NSLOT/128, EE/2);
    dim3 grid2(DD/64, NSLOT/128, EE/2);

    // stream 0: experts 0-3, stream s2: experts 4-7
    cudaStreamWaitEvent(0, evW1, 0);
    cudaStreamWaitEvent(s2, evPlace, 0);
    cudaStreamWaitEvent(s2, evW1, 0);

    gemm_fp8<64, 3, 0, true><<<grid1, 256, DSM64, 0>>>(
        p_xn8, p_w1_8, p_h8, DD, DD, FF, (size_t)FF*DD, 0);
    gemm_fp8<64, 3, 0, true><<<grid1, 256, DSM64, s2>>>(
        p_xn8, p_w1_8, p_h8, DD, DD, FF, (size_t)FF*DD, 4);

    cudaStreamWaitEvent(0, evW2, 0);
    cudaStreamWaitEvent(s2, evW2, 0);

    gemm_fp8<64, 3, 1, false><<<grid2, 256, DSM64, 0>>>(
        p_h8, p_w2_8, p_yh, FF, FF, DD, (size_t)DD*FF, 0);
    gemm_fp8<64, 3, 1, false><<<grid2, 256, DSM64, s2>>>(
        p_h8, p_w2_8, p_yh, FF, FF, DD, (size_t)DD*FF, 4);
    cudaEventRecord(evB, s2);

    cudaStreamWaitEvent(0, evB, 0);
    k_combine<<<TT, 256>>>(x, scale, out, out_size);
}

// round 16
// speedup vs baseline: 1.1693x; 1.1693x over previous
#include <cuda_runtime.h>
#include <cuda_bf16.h>
#include <cuda_fp16.h>
#include <math.h>
#include <stdint.h>

#define TT 2048
#define DD 1024
#define EE 8
#define FF 2048
#define NSLOT (TT*2)
#define NW (EE*FF*DD)

#define S_ACT 16.f
#define S_WGT 512.f
#define INV_ACC (1.f/8192.f)

// ---------------- scratch ----------------
__device__ __align__(16) uint8_t g_xn8[TT*DD];
__device__ __align__(16) uint8_t g_w1_8[NW];
__device__ __align__(16) uint8_t g_w2_8[NW];
__device__ __align__(16) uint8_t g_h8[(size_t)NSLOT*FF];
__device__ __align__(16) __half g_yh[(size_t)NSLOT*DD];
__device__ float g_probs[TT*EE];
__device__ int   g_slot_e[NSLOT];
__device__ float g_slot_w[NSLOT];
__device__ int   g_slot_row[NSLOT];
__device__ int   g_row_tok[NSLOT];
__device__ int   g_n[EE];
__device__ int   g_off[EE];
__device__ int   g_cnt1[EE];

// ================= helpers =================
__device__ __forceinline__ uint32_t smem_u32(const void* p) {
    uint32_t a;
    asm("{ .reg .u64 t; cvta.to.shared.u64 t, %1; cvt.u32.u64 %0, t; }" : "=r"(a) : "l"(p));
    return a;
}
__device__ __forceinline__ void cpa16(uint32_t dst, const void* src) {
    asm volatile("cp.async.cg.shared.global [%0], [%1], 16;" :: "r"(dst), "l"(src) : "memory");
}
#define CP_COMMIT() asm volatile("cp.async.commit_group;" ::: "memory")
#define CP_WAIT1()  asm volatile("cp.async.wait_group 1;" ::: "memory")

__device__ __forceinline__ void ldsm_x4(uint32_t (&r)[4], uint32_t addr) {
    asm volatile("ldmatrix.sync.aligned.m8n8.x4.shared.b16 {%0,%1,%2,%3}, [%4];"
        : "=r"(r[0]), "=r"(r[1]), "=r"(r[2]), "=r"(r[3]) : "r"(addr));
}
__device__ __forceinline__ void mma_fp8h(uint32_t (&d)[2], const uint32_t (&a)[4],
                                         uint32_t b0, uint32_t b1) {
    asm volatile("mma.sync.aligned.m16n8k32.row.col.f16.e4m3.e4m3.f16 "
        "{%0,%1}, {%2,%3,%4,%5}, {%6,%7}, {%0,%1};"
        : "+r"(d[0]), "+r"(d[1])
        : "r"(a[0]), "r"(a[1]), "r"(a[2]), "r"(a[3]), "r"(b0), "r"(b1));
}
__device__ __forceinline__ uint16_t cvt_e4m3x2(float lo, float hi) {
    uint16_t h;
    asm("cvt.rn.satfinite.e4m3x2.f32 %0, %1, %2;" : "=h"(h) : "f"(hi), "f"(lo));
    return h;
}
__device__ __forceinline__ uint32_t rowu_rel(int row, int u) {
    return (uint32_t)row*80u + (uint32_t)((u ^ ((row >> 3) & 3)) * 16);
}
__device__ __forceinline__ float wred(float v) {
#pragma unroll
    for (int d = 16; d > 0; d >>= 1) v += __shfl_down_sync(0xffffffffu, v, d);
    return v;
}

// ---------------- fp32 -> fp8 conversion (one tensor) ------------------------
__global__ void k_cvt8(const float4* __restrict__ in, uint2* __restrict__ outp)
{
    int i = blockIdx.x*256 + threadIdx.x;
    float4 a = in[2*i], b = in[2*i+1];
    uint32_t u0 = (uint32_t)cvt_e4m3x2(a.x*S_WGT, a.y*S_WGT)
                | ((uint32_t)cvt_e4m3x2(a.z*S_WGT, a.w*S_WGT) << 16);
    uint32_t u1 = (uint32_t)cvt_e4m3x2(b.x*S_WGT, b.y*S_WGT)
                | ((uint32_t)cvt_e4m3x2(b.z*S_WGT, b.w*S_WGT) << 16);
    outp[i] = make_uint2(u0, u1);
}

// ---------------- kernel 1: rmsnorm + router ---------------------------------
__global__ void k_norm_router(const float* __restrict__ x,
                              const float* __restrict__ gw,
                              const float* __restrict__ nw)
{
    int t = blockIdx.x, tid = threadIdx.x, lane = tid & 31, w = tid >> 5;
    __shared__ float wss[8];
    __shared__ float wr8[8][8];
    __shared__ float pfin[8];

    const float4* x4 = reinterpret_cast<const float4*>(x) + (size_t)t*256;
    float4 xv = x4[tid];
    float ss = xv.x*xv.x + xv.y*xv.y + xv.z*xv.z + xv.w*xv.w;
    ss = wred(ss);
    if (lane == 0) wss[w] = ss;
    __syncthreads();
    float tot = wss[0]+wss[1]+wss[2]+wss[3]+wss[4]+wss[5]+wss[6]+wss[7];
    float rstd = rsqrtf(tot*(1.0f/1024.0f) + 1.1920928955078125e-07f);

    float4 wv = reinterpret_cast<const float4*>(nw)[tid];
    float4 xn;
    xn.x = xv.x*rstd*wv.x; xn.y = xv.y*rstd*wv.y;
    xn.z = xv.z*rstd*wv.z; xn.w = xv.w*rstd*wv.w;
    uint32_t pk = (uint32_t)cvt_e4m3x2(xn.x*S_ACT, xn.y*S_ACT)
                | ((uint32_t)cvt_e4m3x2(xn.z*S_ACT, xn.w*S_ACT) << 16);
    reinterpret_cast<uint32_t*>(g_xn8)[(size_t)t*256 + tid] = pk;

    const float4* gw4 = reinterpret_cast<const float4*>(gw);
#pragma unroll
    for (int e = 0; e < 8; e++) {
        float4 g = gw4[e*256 + tid];
        float r = xn.x*g.x + xn.y*g.y + xn.z*g.z + xn.w*g.w;
        r = wred(r);
        if (lane == 0) wr8[w][e] = r;
    }
    __syncthreads();
    if (w == 0 && lane < 8) {
        float s = 0.f;
#pragma unroll
        for (int k = 0; k < 8; k++) s += wr8[k][lane];
        pfin[lane] = s;
    }
    __syncthreads();

    if (tid == 0) {
        float p[8]; float m = -1e30f;
#pragma unroll
        for (int e = 0; e < 8; e++) { p[e] = pfin[e]; m = fmaxf(m, p[e]); }
        float s = 0.f;
#pragma unroll
        for (int e = 0; e < 8; e++) { p[e] = expf(p[e]-m); s += p[e]; }
        float inv = 1.f/s;
#pragma unroll
        for (int e = 0; e < 8; e++) { p[e] *= inv; g_probs[t*8+e] = p[e]; }
        int e0 = 0;
#pragma unroll
        for (int e = 1; e < 8; e++) if (p[e] > p[e0]) e0 = e;
        int e1 = (e0 == 0) ? 1 : 0;
#pragma unroll
        for (int e = 0; e < 8; e++) if (e != e0 && p[e] > p[e1]) e1 = e;
        float swt = fmaxf(p[e0] + p[e1], 1e-6f);
        g_slot_e[2*t]   = e0; g_slot_e[2*t+1] = e1;
        g_slot_w[2*t]   = p[e0]/swt;
        g_slot_w[2*t+1] = p[e1]/swt;
    }
}

// -------- kernel 2: count + offsets + stable placement -----------------------
__global__ void k_place()
{
    int e = blockIdx.x, tid = threadIdx.x, lane = tid & 31, w = tid >> 5;
    __shared__ int tot[8];
    __shared__ int c1tot;
    __shared__ int wsum[8];

    int se[16];
    int c8[8] = {0,0,0,0,0,0,0,0};
    int c1 = 0;
    int base_i = tid * 16;
#pragma unroll
    for (int j = 0; j < 16; j++) {
        int s = g_slot_e[base_i + j];
        se[j] = s;
        c8[s]++;
        if ((((base_i + j) & 1) == 0) && s == e) c1++;
    }
    int cnt = c8[e];
    if (tid < 8) tot[tid] = 0;
    if (tid == 0) c1tot = 0;
    __syncthreads();
#pragma unroll
    for (int k = 0; k < 8; k++) if (c8[k]) atomicAdd(&tot[k], c8[k]);
    if (c1) atomicAdd(&c1tot, c1);

    int pre = cnt;
#pragma unroll
    for (int d = 1; d < 32; d <<= 1) {
        int v = __shfl_up_sync(0xffffffffu, pre, d);
        if (lane >= d) pre += v;
    }
    if (lane == 31) wsum[w] = pre;
    __syncthreads();

    int woff = 0;
#pragma unroll
    for (int k = 0; k < 8; k++) if (k < w) woff += wsum[k];
    int excl = woff + pre - cnt;

    int base = 0;
#pragma unroll
    for (int k = 0; k < 8; k++) if (k < e) base += tot[k];
    if (tid == 0) { g_n[e] = tot[e]; g_off[e] = base; g_cnt1[e] = c1tot; }

    int pos = base + excl;
#pragma unroll
    for (int j = 0; j < 16; j++) {
        if (se[j] == e) {
            g_slot_row[base_i + j] = pos;
            g_row_tok[pos] = (base_i + j) >> 1;
            pos++;
        }
    }
}

// ---------------- grouped fp8 GEMM, f16 acc, 3-stage ring --------------------
// TILE_N: CTA N tile (128 or 64). Warp layout 2 row x 4 col, warp tile 64 x TILE_N/4.
// OUTMODE: 0 = silu + fp8 out (gemm1), 1 = f16 out (gemm2).
template<int TILE_N, int MINB, int OUTMODE, bool GATHER>
__global__ void __launch_bounds__(256, MINB) gemm_fp8(
    const uint8_t* __restrict__ A,
    const uint8_t* __restrict__ Bw,
    void* __restrict__ Cv,
    int ldaB, int kdB, int ldc, size_t bstrideB, int ebase)
{
    constexpr int WT_N = TILE_N / 4;          // 32 or 16
    constexpr int NI   = WT_N / 8;            // 4 or 2
    constexpr int NB   = (NI + 1) / 2;        // 2 or 1
    constexpr int BSEG = TILE_N / 64;         // 2 or 1 (16B units per thread)
    constexpr uint32_t STG = (uint32_t)(128 + TILE_N) * 80u;
    constexpr uint32_t RING = 3u * STG;
    constexpr uint32_t bOff = 128 * 80;

    int e = ebase + blockIdx.z;
    int n_e = g_n[e];
    int rowBase = blockIdx.y * 128;
    if (rowBase >= n_e) return;
    int off = g_off[e];
    int colBase = blockIdx.x * TILE_N;

    extern __shared__ char smraw[];
    uint32_t sm0 = smem_u32(smraw);

    int tid = threadIdx.x, wid = tid >> 5, lane = tid & 31;
    int rowWarp = wid & 1, colWarp = wid >> 1;

    // A loads: 128 rows x 4 units, 2 units/thread
    int aR = tid >> 1;
    int aS = (tid & 1) * 2;
    const uint8_t* aRow;
    {
        int src;
        if (GATHER) src = (rowBase + aR < n_e) ? g_row_tok[off + rowBase + aR] : 0;
        else { int gr = off + rowBase + aR; src = (gr < NSLOT) ? gr : 0; }
        aRow = A + (size_t)src * ldaB + aS*16;
    }
    uint32_t aDst0 = sm0 + rowu_rel(aR, aS);
    uint32_t aDst1 = sm0 + rowu_rel(aR, aS + 1);

    // B loads: TILE_N rows x 4 units, BSEG units/thread
    int bR = (BSEG == 2) ? (tid >> 1) : (tid >> 2);
    int bS = (BSEG == 2) ? ((tid & 1) * 2) : (tid & 3);
    const uint8_t* bRow = Bw + (size_t)e * bstrideB + (size_t)(colBase + bR) * kdB + bS*16;
    uint32_t bDst[BSEG];
#pragma unroll
    for (int j = 0; j < BSEG; j++) bDst[j] = sm0 + bOff + rowu_rel(bR, bS + j);

    // ldmatrix lane addresses
    int lr = lane & 15, hiU = lane >> 4;
    int nl = (lane & 7) + ((lane & 16) ? 8 : 0);
    int kcU = (lane >> 3) & 1;
    uint32_t aAddr[2][4], bAddr[2][NB];
#pragma unroll
    for (int ks = 0; ks < 2; ks++) {
#pragma unroll
        for (int mi = 0; mi < 4; mi++)
            aAddr[ks][mi] = sm0 + rowu_rel(rowWarp*64 + mi*16 + lr, ks*2 + hiU);
#pragma unroll
        for (int nb = 0; nb < NB; nb++)
            bAddr[ks][nb] = sm0 + bOff + rowu_rel(colWarp*WT_N + nb*16 + nl, ks*2 + kcU);
    }

    uint32_t acc[4][NI][2];
#pragma unroll
    for (int mi = 0; mi < 4; mi++)
#pragma unroll
        for (int ni = 0; ni < NI; ni++) { acc[mi][ni][0] = 0u; acc[mi][ni][1] = 0u; }

    int nch = kdB >> 6;

#define ISSUE(KB, SO) do { \
    const uint8_t* _as = aRow + (KB)*64; \
    cpa16(aDst0 + (SO), _as); cpa16(aDst1 + (SO), _as + 16); \
    const uint8_t* _bs = bRow + (KB)*64; \
    _Pragma("unroll") \
    for (int _j = 0; _j < BSEG; _j++) cpa16(bDst[_j] + (SO), _bs + _j*16); \
    CP_COMMIT(); } while (0)

    ISSUE(0, 0u); ISSUE(1, STG);

    uint32_t soC = 0, soI = 2u * STG;
    for (int kb = 0; kb < nch; kb++) {
        CP_WAIT1();
        __syncthreads();
        if (kb + 2 < nch) { ISSUE(kb + 2, soI); } else { CP_COMMIT(); }
        soI += STG; if (soI == RING) soI = 0;

#pragma unroll
        for (int ks = 0; ks < 2; ks++) {
            uint32_t af[4][4], bf[NB][4];
#pragma unroll
            for (int mi = 0; mi < 4; mi++)
                ldsm_x4(af[mi], aAddr[ks][mi] + soC);
#pragma unroll
            for (int nb = 0; nb < NB; nb++)
                ldsm_x4(bf[nb], bAddr[ks][nb] + soC);
#pragma unroll
            for (int mi = 0; mi < 4; mi++) {
#pragma unroll
                for (int ni = 0; ni < NI; ni++)
                    mma_fp8h(acc[mi][ni], af[mi], bf[ni>>1][(ni&1)*2], bf[ni>>1][(ni&1)*2+1]);
            }
        }
        soC += STG; if (soC == RING) soC = 0;
    }
#undef ISSUE

    int g  = lane >> 2;
    int tq = lane & 3;
    const __half2 hInv = __float2half2_rn(INV_ACC);
#pragma unroll
    for (int mi = 0; mi < 4; mi++) {
#pragma unroll
        for (int half_ = 0; half_ < 2; half_++) {
            int rr = rowBase + rowWarp*64 + mi*16 + half_*8 + g;
            if (rr >= n_e) continue;
            size_t rowOff = (size_t)(off + rr) * ldc;
#pragma unroll
            for (int ni = 0; ni < NI; ni++) {
                int c = colBase + colWarp*WT_N + ni*8 + tq*2;
                __half2 hv = *reinterpret_cast<__half2*>(&acc[mi][ni][half_]);
                if (OUTMODE == 0) {
                    float2 f = __half22float2(hv);
                    float v0 = f.x * INV_ACC;
                    float v1 = f.y * INV_ACC;
                    v0 = v0 / (1.f + expf(-v0));
                    v1 = v1 / (1.f + expf(-v1));
                    uint16_t hq = cvt_e4m3x2(v0*S_ACT, v1*S_ACT);
                    *reinterpret_cast<uint16_t*>(
                        reinterpret_cast<uint8_t*>(Cv) + rowOff + c) = hq;
                } else {
                    __half2 y = __hmul2(hv, hInv);
                    *reinterpret_cast<__half2*>(
                        reinterpret_cast<__half*>(Cv) + rowOff + c) = y;
                }
            }
        }
    }
}

// ---------------- residual + weighted combine (+ lb loss) --------------------
__global__ void k_combine(const float* __restrict__ x,
                          const float* __restrict__ scale,
                          float* __restrict__ out, int out_size)
{
    int t = blockIdx.x, q = threadIdx.x;
    float sc = 1.f / (1.f + expf(-scale[0]));
    int   r0 = g_slot_row[2*t],   r1 = g_slot_row[2*t+1];
    float w0 = g_slot_w[2*t],     w1 = g_slot_w[2*t+1];
    const float4* x4 = reinterpret_cast<const float4*>(x);
    const __half2* y2 = reinterpret_cast<const __half2*>(g_yh);
    float4 xv = x4[(size_t)t*256 + q];
    __half2 a0 = y2[(size_t)r0*512 + q*2],  a1 = y2[(size_t)r0*512 + q*2 + 1];
    __half2 b0 = y2[(size_t)r1*512 + q*2],  b1 = y2[(size_t)r1*512 + q*2 + 1];
    float2 fa0 = __half22float2(a0), fa1 = __half22float2(a1);
    float2 fb0 = __half22float2(b0), fb1 = __half22float2(b1);
    float4 o;
    o.x = xv.x + sc*(w0*fa0.x + w1*fb0.x);
    o.y = xv.y + sc*(w0*fa0.y + w1*fb0.y);
    o.z = xv.z + sc*(w0*fa1.x + w1*fb1.x);
    o.w = xv.w + sc*(w0*fa1.y + w1*fb1.y);
    reinterpret_cast<float4*>(out)[(size_t)t*256 + q] = o;

    if (t == 0 && out_size > TT*DD) {
        __shared__ float r8[8*256];
        float p[8] = {0.f,0.f,0.f,0.f,0.f,0.f,0.f,0.f};
        for (int tt = q; tt < TT; tt += 256) {
#pragma unroll
            for (int e = 0; e < 8; e++) p[e] += g_probs[tt*8+e];
        }
#pragma unroll
        for (int e = 0; e < 8; e++) r8[e*256+q] = p[e];
        __syncthreads();
        for (int s = 128; s > 0; s >>= 1) {
            if (q < s) {
#pragma unroll
                for (int e = 0; e < 8; e++) r8[e*256+q] += r8[e*256+q+s];
            }
            __syncthreads();
        }
        if (q == 0) {
            float lb = 0.f;
            for (int e = 0; e < 8; e++) {
                float fe = (float)g_cnt1[e] * (1.f/(float)TT);
                float pm = r8[e*256] * (1.f/(float)TT);
                lb += fe * pm;
            }
            out[(size_t)TT*DD] = 8.f * lb;
        }
    }
}

// ------ launch: R14 configuration (best measured: 200.6 us) ------------------
extern "C" void kernel_launch(void* const* d_in, const int* in_sizes, int n_in,
                              void* d_out, int out_size)
{
    const float* x     = (const float*)d_in[0];
    const float* gw    = (const float*)d_in[1];
    const float* w1    = (const float*)d_in[2];
    const float* w2    = (const float*)d_in[3];
    const float* nw    = (const float*)d_in[4];
    const float* scale = (const float*)d_in[5];
    float* out = (float*)d_out;

    uint8_t *p_xn8, *p_w1_8, *p_w2_8, *p_h8;
    __half *p_yh;
    cudaGetSymbolAddress((void**)&p_xn8,  g_xn8);
    cudaGetSymbolAddress((void**)&p_w1_8, g_w1_8);
    cudaGetSymbolAddress((void**)&p_w2_8, g_w2_8);
    cudaGetSymbolAddress((void**)&p_h8,   g_h8);
    cudaGetSymbolAddress((void**)&p_yh,   g_yh);

    const int DSM1 = (128 + 128) * 80 * 3;   // 61440  gemm1 (TILE_N=128)
    const int DSM2 = (128 + 64)  * 80 * 3;   // 46080  gemm2 (TILE_N=64)
    static cudaStream_t s1, s2;
    static cudaEvent_t evFork, evW1, evW2, evPlace, evB;
    static bool init_done = false;
    if (!init_done) {
        cudaFuncSetAttribute((const void*)gemm_fp8<128, 3, 0, true >,
                             cudaFuncAttributeMaxDynamicSharedMemorySize, DSM1);
        cudaFuncSetAttribute((const void*)gemm_fp8<64,  3, 1, false>,
                             cudaFuncAttributeMaxDynamicSharedMemorySize, DSM2);
        cudaStreamCreateWithFlags(&s1, cudaStreamNonBlocking);
        cudaStreamCreateWithFlags(&s2, cudaStreamNonBlocking);
        cudaEventCreateWithFlags(&evFork,  cudaEventDisableTiming);
        cudaEventCreateWithFlags(&evW1,    cudaEventDisableTiming);
        cudaEventCreateWithFlags(&evW2,    cudaEventDisableTiming);
        cudaEventCreateWithFlags(&evPlace, cudaEventDisableTiming);
        cudaEventCreateWithFlags(&evB,     cudaEventDisableTiming);
        init_done = true;
    }

    // fork: weight conversion on side stream s1
    cudaEventRecord(evFork, 0);
    cudaStreamWaitEvent(s1, evFork, 0);
    k_cvt8<<<NW/8/256, 256, 0, s1>>>((const float4*)w1, (uint2*)p_w1_8);
    cudaEventRecord(evW1, s1);
    k_cvt8<<<NW/8/256, 256, 0, s1>>>((const float4*)w2, (uint2*)p_w2_8);
    cudaEventRecord(evW2, s1);

    // main: norm + router + placement
    k_norm_router<<<TT, 256>>>(x, gw, nw);
    k_place<<<EE, 256>>>();
    cudaEventRecord(evPlace, 0);

    dim3 grid1(FF/128, NSLOT/128, EE/2);
    dim3 grid2(DD/64,  NSLOT/128, EE/2);

    // stream 0: experts 0-3, stream s2: experts 4-7
    cudaStreamWaitEvent(0, evW1, 0);
    cudaStreamWaitEvent(s2, evPlace, 0);
    cudaStreamWaitEvent(s2, evW1, 0);

    gemm_fp8<128, 3, 0, true><<<grid1, 256, DSM1, 0>>>(
        p_xn8, p_w1_8, p_h8, DD, DD, FF, (size_t)FF*DD, 0);
    gemm_fp8<128, 3, 0, true><<<grid1, 256, DSM1, s2>>>(
        p_xn8, p_w1_8, p_h8, DD, DD, FF, (size_t)FF*DD, 4);

    cudaStreamWaitEvent(0, evW2, 0);
    cudaStreamWaitEvent(s2, evW2, 0);

    gemm_fp8<64, 3, 1, false><<<grid2, 256, DSM2, 0>>>(
        p_h8, p_w2_8, p_yh, FF, FF, DD, (size_t)DD*FF, 0);
    gemm_fp8<64, 3, 1, false><<<grid2, 256, DSM2, s2>>>(
        p_h8, p_w2_8, p_yh, FF, FF, DD, (size_t)DD*FF, 4);
    cudaEventRecord(evB, s2);

    cudaStreamWaitEvent(0, evB, 0);
    k_combine<<<TT, 256>>>(x, scale, out, out_size);
}